// round 1
// baseline (speedup 1.0000x reference)
#include <cuda_runtime.h>

// SpatialTransformer: per-depth-slice 2D bilinear warp, align_corners=True,
// zero padding. Shapes: src [B,C,D,H,W] f32, v [B,2,D,H,W] f32, out [B,C,D,H,W] f32.
// Since H==W, the reference's (W-1)/(H-1) normalization cancel is exact:
//   ix = w + vx, iy = h + vy.

constexpr int B = 8, C = 4, D = 32, H = 256, W = 256;
constexpr int HW = H * W;
constexpr int VEC = 4;                       // pixels per thread
constexpr int NTHREADS_TOTAL = B * D * HW / VEC;  // 4,194,304

__global__ __launch_bounds__(256)
void spatial_transformer_kernel(const float* __restrict__ src,
                                const float* __restrict__ v,
                                float* __restrict__ out)
{
    int t = blockIdx.x * blockDim.x + threadIdx.x;
    if (t >= NTHREADS_TOTAL) return;

    // Decompose: t -> (b, d, h, w4)
    int wq   = t % (W / VEC);
    int rest = t / (W / VEC);
    int h    = rest % H;  rest /= H;
    int d    = rest % D;
    int b    = rest / D;
    int w0   = wq * VEC;

    // v: [B, 2, D, H, W]; vx plane then vy plane
    const int vbase = ((b * 2) * D + d) * HW + h * W + w0;
    const float4 vx4 = *reinterpret_cast<const float4*>(v + vbase);
    const float4 vy4 = *reinterpret_cast<const float4*>(v + vbase + D * HW);

    float vxs[VEC] = {vx4.x, vx4.y, vx4.z, vx4.w};
    float vys[VEC] = {vy4.x, vy4.y, vy4.z, vy4.w};

    // Per-pixel corner offsets (clamped) and weights (validity folded in).
    int   o00[VEC], o01[VEC], o10[VEC], o11[VEC];
    float k00[VEC], k01[VEC], k10[VEC], k11[VEC];

#pragma unroll
    for (int p = 0; p < VEC; p++) {
        float ix = (float)(w0 + p) + vxs[p];
        float iy = (float)h        + vys[p];
        float x0f = floorf(ix);
        float y0f = floorf(iy);
        float fx = ix - x0f;        // weight toward x1
        float fy = iy - y0f;        // weight toward y1
        int x0 = (int)x0f, y0 = (int)y0f;
        int x1 = x0 + 1,   y1 = y0 + 1;

        // validity (zero padding) folded into weights
        float mx0 = (x0 >= 0 && x0 < W) ? 1.0f : 0.0f;
        float mx1 = (x1 >= 0 && x1 < W) ? 1.0f : 0.0f;
        float my0 = (y0 >= 0 && y0 < H) ? 1.0f : 0.0f;
        float my1 = (y1 >= 0 && y1 < H) ? 1.0f : 0.0f;

        int x0c = min(max(x0, 0), W - 1);
        int x1c = min(max(x1, 0), W - 1);
        int y0c = min(max(y0, 0), H - 1);
        int y1c = min(max(y1, 0), H - 1);

        o00[p] = y0c * W + x0c;
        o01[p] = y0c * W + x1c;
        o10[p] = y1c * W + x0c;
        o11[p] = y1c * W + x1c;

        float gx0 = 1.0f - fx, gy0 = 1.0f - fy;
        k00[p] = gx0 * gy0 * (mx0 * my0);
        k01[p] = fx  * gy0 * (mx1 * my0);
        k10[p] = gx0 * fy  * (mx0 * my1);
        k11[p] = fx  * fy  * (mx1 * my1);
    }

    // Reuse offsets/weights across the C=4 channels.
#pragma unroll
    for (int c = 0; c < C; c++) {
        const float* sp = src + (((b * C + c) * D + d) * HW);
        float4 o;
        float* op = &o.x;
#pragma unroll
        for (int p = 0; p < VEC; p++) {
            float acc;
            acc  = __ldg(sp + o00[p]) * k00[p];
            acc += __ldg(sp + o01[p]) * k01[p];
            acc += __ldg(sp + o10[p]) * k10[p];
            acc += __ldg(sp + o11[p]) * k11[p];
            op[p] = acc;
        }
        *reinterpret_cast<float4*>(out + (((b * C + c) * D + d) * HW) + h * W + w0) = o;
    }
}

extern "C" void kernel_launch(void* const* d_in, const int* in_sizes, int n_in,
                              void* d_out, int out_size)
{
    const float* src = (const float*)d_in[0];
    const float* v   = (const float*)d_in[1];
    float* out       = (float*)d_out;

    constexpr int TPB = 256;
    constexpr int BLOCKS = NTHREADS_TOTAL / TPB;  // 16384
    spatial_transformer_kernel<<<BLOCKS, TPB>>>(src, v, out);
}

// round 2
// speedup vs baseline: 1.4477x; 1.4477x over previous
#include <cuda_runtime.h>

// SpatialTransformer: per-depth-slice 2D bilinear warp, align_corners=True,
// zero padding. src [B,C,D,H,W] f32, v [B,2,D,H,W] f32, out [B,C,D,H,W] f32.
// H==W so the reference's (W-1)/(H-1) normalization cancels: ix=w+vx, iy=h+vy.
//
// Key layout decision: each warp owns 128 consecutive pixels of one row; a
// thread owns 4 pixels at stride 32 (x = seg + lane + 32*p). Every gather
// LDG.32 therefore has lane-consecutive addresses (~1-2 L1 wavefronts)
// instead of the stride-4 pattern (4-5 wavefronts) of the previous version.

constexpr int B = 8, C = 4, D = 32, H = 256, W = 256;
constexpr int HW = H * W;
constexpr int PPT = 4;              // pixels per thread (stride 32)
constexpr int TPB = 256;            // 8 warps
constexpr int PIX_PER_WARP = 32 * PPT;          // 128
constexpr long long TOTAL_PX = (long long)B * D * HW;   // 16,777,216
constexpr int TOTAL_WARPS = (int)(TOTAL_PX / PIX_PER_WARP);  // 131,072
constexpr int NBLOCKS = TOTAL_WARPS / (TPB / 32);            // 16,384

__global__ __launch_bounds__(TPB)
void spatial_transformer_kernel(const float* __restrict__ src,
                                const float* __restrict__ v,
                                float* __restrict__ out)
{
    const int gw   = blockIdx.x * (TPB / 32) + (threadIdx.x >> 5);
    const int lane = threadIdx.x & 31;

    // warp's base pixel in flattened [B*D, H, W] space; 128-aligned within a row
    const int base = gw * PIX_PER_WARP;
    const int bd   = base / HW;          // 0..B*D-1
    const int rem  = base % HW;
    const int y    = rem / W;
    const int xseg = rem % W;            // 0 or 128
    const int b    = bd / D;
    const int d    = bd % D;

    // plane bases
    const int vrow   = ((b * 2) * D + d) * HW + y * W + xseg + lane; // vx; +D*HW -> vy
    const int srow   = (b * C * D + d) * HW;                         // + c*D*HW per channel
    const int orow_y = y * W + xseg + lane;

    const float fy_base = (float)y;

#pragma unroll
    for (int p = 0; p < PPT; p++) {
        const int xo = 32 * p;
        const float vx = __ldg(v + vrow + xo);
        const float vy = __ldg(v + vrow + xo + D * HW);

        const float ix = (float)(xseg + lane + xo) + vx;
        const float iy = fy_base + vy;

        const float x0f = floorf(ix);
        const float y0f = floorf(iy);
        const float fx  = ix - x0f;          // weight toward x1
        const float fyw = iy - y0f;          // weight toward y1
        const int x0 = (int)x0f, y0 = (int)y0f;
        const int x1 = x0 + 1,   y1 = y0 + 1;

        // zero-padding validity folded into weights
        const float mx0 = (x0 >= 0 && x0 < W) ? 1.0f : 0.0f;
        const float mx1 = (x1 >= 0 && x1 < W) ? 1.0f : 0.0f;
        const float my0 = (y0 >= 0 && y0 < H) ? 1.0f : 0.0f;
        const float my1 = (y1 >= 0 && y1 < H) ? 1.0f : 0.0f;

        const int x0c = min(max(x0, 0), W - 1);
        const int x1c = min(max(x1, 0), W - 1);
        const int y0c = min(max(y0, 0), H - 1);
        const int y1c = min(max(y1, 0), H - 1);

        const int o00 = y0c * W + x0c;
        const int o01 = y0c * W + x1c;
        const int o10 = y1c * W + x0c;
        const int o11 = y1c * W + x1c;

        const float gx0 = 1.0f - fx, gy0 = 1.0f - fyw;
        const float k00 = gx0 * gy0 * (mx0 * my0);
        const float k01 = fx  * gy0 * (mx1 * my0);
        const float k10 = gx0 * fyw * (mx0 * my1);
        const float k11 = fx  * fyw * (mx1 * my1);

#pragma unroll
        for (int c = 0; c < C; c++) {
            const float* sp = src + srow + c * (D * HW);
            float acc;
            acc  =        __ldg(sp + o00) * k00;
            acc  = fmaf(  __ldg(sp + o01),  k01, acc);
            acc  = fmaf(  __ldg(sp + o10),  k10, acc);
            acc  = fmaf(  __ldg(sp + o11),  k11, acc);
            out[srow + c * (D * HW) + orow_y + xo] = acc;
        }
    }
}

extern "C" void kernel_launch(void* const* d_in, const int* in_sizes, int n_in,
                              void* d_out, int out_size)
{
    const float* src = (const float*)d_in[0];
    const float* v   = (const float*)d_in[1];
    float* out       = (float*)d_out;

    spatial_transformer_kernel<<<NBLOCKS, TPB>>>(src, v, out);
}

// round 3
// speedup vs baseline: 1.6650x; 1.1501x over previous
#include <cuda_runtime.h>
#include <cstdint>

// SpatialTransformer: 2D bilinear warp per depth slice, align_corners=True,
// zero padding. src [B,C,D,H,W] f32, v [B,2,D,H,W] f32, out f32.
// H==W so normalization cancels: ix = x + vx, iy = y + vy.
//
// Strategy: TMA-stage a row band of all 4 channel planes into SMEM, gather
// with LDS (bank = x mod 32 -> conflict-free regardless of row jitter),
// rare out-of-band rows fall back to global __ldg.

constexpr int B = 8, C = 4, D = 32, H = 256, W = 256;
constexpr int HW  = H * W;
constexpr int DHW = D * HW;
constexpr int RB  = 8;                 // output rows per block
constexpr int MGN = 4;                 // staged row margin (|vy|<=4 fast path)
constexpr int TRMAX = RB + 2 * MGN;    // 16 staged rows max
constexpr int TPB = 256;               // 8 warps; 1 output row per warp
constexpr int P   = 8;                 // pixels per thread, x stride 32
constexpr int TILE_ELEMS = TRMAX * W;  // 4096 floats per channel
constexpr int NBLK = B * D * (H / RB); // 8192
constexpr size_t SMEM_BYTES = (size_t)C * TILE_ELEMS * 4 + 16;

__device__ __forceinline__ uint32_t s2u(const void* p) {
    return (uint32_t)__cvta_generic_to_shared(p);
}

__global__ __launch_bounds__(TPB, 2)
void st_kernel(const float* __restrict__ src,
               const float* __restrict__ v,
               float* __restrict__ out)
{
    extern __shared__ float smem[];
    float* tile = smem;  // [C][TILE_ELEMS]
    unsigned long long* mbar = (unsigned long long*)(smem + C * TILE_ELEMS);

    const int blk = blockIdx.x;
    const int rt  = blk & (H / RB - 1);   // H/RB = 32
    const int bd  = blk >> 5;
    const int d   = bd & (D - 1);         // D = 32
    const int b   = bd >> 5;
    const int r0  = rt * RB;
    const int r_lo = max(0, r0 - MGN);
    const int r_hi = min(H, r0 + RB + MGN);
    const int nrows = r_hi - r_lo;

    const float* splane = src + (size_t)(b * C) * DHW + (size_t)d * HW;

    const uint32_t mb = s2u(mbar);
    if (threadIdx.x == 0) {
        asm volatile("mbarrier.init.shared.b64 [%0], 1;" :: "r"(mb) : "memory");
    }
    __syncthreads();
    if (threadIdx.x == 0) {
        const int bytes = nrows * W * 4;
        asm volatile("mbarrier.arrive.expect_tx.shared.b64 _, [%0], %1;"
                     :: "r"(mb), "r"(bytes * C) : "memory");
#pragma unroll
        for (int c = 0; c < C; c++) {
            const uint32_t dst = s2u(tile + c * TILE_ELEMS);
            const float* gsrc = splane + (size_t)c * DHW + r_lo * W;
            asm volatile(
                "cp.async.bulk.shared::cluster.global.mbarrier::complete_tx::bytes "
                "[%0], [%1], %2, [%3];"
                :: "r"(dst), "l"(gsrc), "r"(bytes), "r"(mb) : "memory");
        }
    }

    // ---- coordinate phase (overlaps the TMA) ----
    const int warp = threadIdx.x >> 5, lane = threadIdx.x & 31;
    const int y = r0 + warp;
    const float* vx_row = v + (size_t)(b * 2) * DHW + (size_t)d * HW + y * W;
    const float* vy_row = vx_row + DHW;

    int   o00[P], o01[P], o10[P], o11[P];
    float k00[P], k01[P], k10[P], k11[P];

#pragma unroll
    for (int p = 0; p < P; p++) {
        const int x = lane + 32 * p;
        const float vx = __ldg(vx_row + x);
        const float vy = __ldg(vy_row + x);
        const float ix = (float)x + vx;
        const float iy = (float)y + vy;
        const float x0f = floorf(ix), y0f = floorf(iy);
        const float fx = ix - x0f, fy = iy - y0f;
        const int x0 = (int)x0f, y0 = (int)y0f;
        const int x1 = x0 + 1,   y1 = y0 + 1;

        const float mx0 = (x0 >= 0 && x0 < W) ? 1.0f : 0.0f;
        const float mx1 = (x1 >= 0 && x1 < W) ? 1.0f : 0.0f;
        const float my0 = (y0 >= 0 && y0 < H) ? 1.0f : 0.0f;
        const float my1 = (y1 >= 0 && y1 < H) ? 1.0f : 0.0f;

        const int x0c = min(max(x0, 0), W - 1);
        const int x1c = min(max(x1, 0), W - 1);
        const int y0c = min(max(y0, 0), H - 1);
        const int y1c = min(max(y1, 0), H - 1);

        const float gx0 = 1.0f - fx, gy0 = 1.0f - fy;
        k00[p] = gx0 * gy0 * (mx0 * my0);
        k01[p] = fx  * gy0 * (mx1 * my0);
        k10[p] = gx0 * fy  * (mx0 * my1);
        k11[p] = fx  * fy  * (mx1 * my1);

        if (y0c >= r_lo && y1c < r_hi) {
            const int row0 = (y0c - r_lo) * W, row1 = (y1c - r_lo) * W;
            o00[p] = row0 + x0c; o01[p] = row0 + x1c;
            o10[p] = row1 + x0c; o11[p] = row1 + x1c;
        } else {
            // slow path: encode global plane offsets as ~g (negative)
            o00[p] = ~(y0c * W + x0c); o01[p] = ~(y0c * W + x1c);
            o10[p] = ~(y1c * W + x0c); o11[p] = ~(y1c * W + x1c);
        }
    }

    // ---- wait for TMA tiles ----
    {
        uint32_t done;
        do {
            asm volatile(
                "{.reg .pred p; mbarrier.try_wait.parity.acquire.cta.shared::cta.b64 "
                "p, [%1], %2; selp.b32 %0, 1, 0, p;}"
                : "=r"(done) : "r"(mb), "r"(0u) : "memory");
        } while (!done);
    }

    // ---- gather + store ----
    float* obase = out + (size_t)(b * C) * DHW + (size_t)d * HW + y * W;
#pragma unroll
    for (int p = 0; p < P; p++) {
        const int x = lane + 32 * p;
        if (o00[p] >= 0) {
#pragma unroll
            for (int c = 0; c < C; c++) {
                const float* tc = tile + c * TILE_ELEMS;
                float acc =      tc[o00[p]] * k00[p];
                acc = fmaf(tc[o01[p]], k01[p], acc);
                acc = fmaf(tc[o10[p]], k10[p], acc);
                acc = fmaf(tc[o11[p]], k11[p], acc);
                obase[(size_t)c * DHW + x] = acc;
            }
        } else {
            const int g00 = ~o00[p], g01 = ~o01[p];
            const int g10 = ~o10[p], g11 = ~o11[p];
#pragma unroll
            for (int c = 0; c < C; c++) {
                const float* sc = splane + (size_t)c * DHW;
                float acc =      __ldg(sc + g00) * k00[p];
                acc = fmaf(__ldg(sc + g01), k01[p], acc);
                acc = fmaf(__ldg(sc + g10), k10[p], acc);
                acc = fmaf(__ldg(sc + g11), k11[p], acc);
                obase[(size_t)c * DHW + x] = acc;
            }
        }
    }
}

extern "C" void kernel_launch(void* const* d_in, const int* in_sizes, int n_in,
                              void* d_out, int out_size)
{
    const float* src = (const float*)d_in[0];
    const float* v   = (const float*)d_in[1];
    float* out       = (float*)d_out;

    cudaFuncSetAttribute(st_kernel,
                         cudaFuncAttributeMaxDynamicSharedMemorySize,
                         (int)SMEM_BYTES);
    st_kernel<<<NBLK, TPB, SMEM_BYTES>>>(src, v, out);
}

// round 4
// speedup vs baseline: 1.6940x; 1.0175x over previous
#include <cuda_runtime.h>
#include <cstdint>

// SpatialTransformer: 2D bilinear warp per depth slice, align_corners=True,
// zero padding. src [B,C,D,H,W] f32, v [B,2,D,H,W] f32, out f32.
// H==W so normalization cancels: ix = x + vx, iy = y + vy.
//
// TMA-stage a row band of all 4 channel planes into SMEM, gather with LDS
// (bank = x mod 32, near-conflict-free), rare out-of-band rows (|vy|>4)
// fall back to global __ldg. Coord work is split in two halves so register
// pressure stays <= 85 and 3 blocks fit per SM (occupancy was the R3 limiter).

constexpr int B = 8, C = 4, D = 32, H = 256, W = 256;
constexpr int HW  = H * W;
constexpr int DHW = D * HW;
constexpr int RB  = 8;                 // output rows per block
constexpr int MGN = 4;                 // staged row margin (|vy|<=4 fast path)
constexpr int TRMAX = RB + 2 * MGN;    // 16 staged rows max
constexpr int TPB = 256;               // 8 warps; 1 output row per warp
constexpr int HP  = 4;                 // pixels per half (2 halves = 8 px/thread)
constexpr int TILE_ELEMS = TRMAX * W;  // 4096 floats per channel
constexpr int NBLK = B * D * (H / RB); // 8192
constexpr size_t SMEM_BYTES = (size_t)C * TILE_ELEMS * 4 + 16;

__device__ __forceinline__ uint32_t s2u(const void* p) {
    return (uint32_t)__cvta_generic_to_shared(p);
}

struct Coords {
    int   o00[HP], o01[HP], o10[HP], o11[HP];
    float k00[HP], k01[HP], k10[HP], k11[HP];
};

__device__ __forceinline__ void compute_coords(
    Coords& cc, const float* __restrict__ vx_row, const float* __restrict__ vy_row,
    int lane, int y, int p0, int r_lo, int r_hi)
{
#pragma unroll
    for (int p = 0; p < HP; p++) {
        const int x = lane + 32 * (p0 + p);
        const float vx = __ldg(vx_row + x);
        const float vy = __ldg(vy_row + x);
        const float ix = (float)x + vx;
        const float iy = (float)y + vy;
        const float x0f = floorf(ix), y0f = floorf(iy);
        const float fx = ix - x0f, fy = iy - y0f;
        const int x0 = (int)x0f, y0 = (int)y0f;
        const int x1 = x0 + 1,   y1 = y0 + 1;

        const float mx0 = (x0 >= 0 && x0 < W) ? 1.0f : 0.0f;
        const float mx1 = (x1 >= 0 && x1 < W) ? 1.0f : 0.0f;
        const float my0 = (y0 >= 0 && y0 < H) ? 1.0f : 0.0f;
        const float my1 = (y1 >= 0 && y1 < H) ? 1.0f : 0.0f;

        const int x0c = min(max(x0, 0), W - 1);
        const int x1c = min(max(x1, 0), W - 1);
        const int y0c = min(max(y0, 0), H - 1);
        const int y1c = min(max(y1, 0), H - 1);

        const float gx0 = 1.0f - fx, gy0 = 1.0f - fy;
        cc.k00[p] = gx0 * gy0 * (mx0 * my0);
        cc.k01[p] = fx  * gy0 * (mx1 * my0);
        cc.k10[p] = gx0 * fy  * (mx0 * my1);
        cc.k11[p] = fx  * fy  * (mx1 * my1);

        if (y0c >= r_lo && y1c < r_hi) {
            const int row0 = (y0c - r_lo) * W, row1 = (y1c - r_lo) * W;
            cc.o00[p] = row0 + x0c; cc.o01[p] = row0 + x1c;
            cc.o10[p] = row1 + x0c; cc.o11[p] = row1 + x1c;
        } else {
            // slow path: encode global plane offsets as ~g (negative)
            cc.o00[p] = ~(y0c * W + x0c); cc.o01[p] = ~(y0c * W + x1c);
            cc.o10[p] = ~(y1c * W + x0c); cc.o11[p] = ~(y1c * W + x1c);
        }
    }
}

__device__ __forceinline__ void gather_store(
    const Coords& cc, const float* __restrict__ tile,
    const float* __restrict__ splane, float* __restrict__ obase,
    int lane, int p0)
{
#pragma unroll
    for (int p = 0; p < HP; p++) {
        const int x = lane + 32 * (p0 + p);
        if (cc.o00[p] >= 0) {
#pragma unroll
            for (int c = 0; c < C; c++) {
                const float* tc = tile + c * TILE_ELEMS;
                float acc =      tc[cc.o00[p]] * cc.k00[p];
                acc = fmaf(tc[cc.o01[p]], cc.k01[p], acc);
                acc = fmaf(tc[cc.o10[p]], cc.k10[p], acc);
                acc = fmaf(tc[cc.o11[p]], cc.k11[p], acc);
                obase[(size_t)c * DHW + x] = acc;
            }
        } else {
            const int g00 = ~cc.o00[p], g01 = ~cc.o01[p];
            const int g10 = ~cc.o10[p], g11 = ~cc.o11[p];
#pragma unroll
            for (int c = 0; c < C; c++) {
                const float* sc = splane + (size_t)c * DHW;
                float acc =      __ldg(sc + g00) * cc.k00[p];
                acc = fmaf(__ldg(sc + g01), cc.k01[p], acc);
                acc = fmaf(__ldg(sc + g10), cc.k10[p], acc);
                acc = fmaf(__ldg(sc + g11), cc.k11[p], acc);
                obase[(size_t)c * DHW + x] = acc;
            }
        }
    }
}

__global__ __launch_bounds__(TPB, 3)
void st_kernel(const float* __restrict__ src,
               const float* __restrict__ v,
               float* __restrict__ out)
{
    extern __shared__ float smem[];
    float* tile = smem;  // [C][TILE_ELEMS]
    unsigned long long* mbar = (unsigned long long*)(smem + C * TILE_ELEMS);

    const int blk = blockIdx.x;
    const int rt  = blk & (H / RB - 1);   // 32 row-tiles
    const int bd  = blk >> 5;
    const int d   = bd & (D - 1);
    const int b   = bd >> 5;
    const int r0  = rt * RB;
    const int r_lo = max(0, r0 - MGN);
    const int r_hi = min(H, r0 + RB + MGN);
    const int nrows = r_hi - r_lo;

    const float* splane = src + (size_t)(b * C) * DHW + (size_t)d * HW;

    const uint32_t mb = s2u(mbar);
    if (threadIdx.x == 0) {
        asm volatile("mbarrier.init.shared.b64 [%0], 1;" :: "r"(mb) : "memory");
    }
    __syncthreads();
    if (threadIdx.x == 0) {
        const int bytes = nrows * W * 4;
        asm volatile("mbarrier.arrive.expect_tx.shared.b64 _, [%0], %1;"
                     :: "r"(mb), "r"(bytes * C) : "memory");
#pragma unroll
        for (int c = 0; c < C; c++) {
            const uint32_t dst = s2u(tile + c * TILE_ELEMS);
            const float* gsrc = splane + (size_t)c * DHW + r_lo * W;
            asm volatile(
                "cp.async.bulk.shared::cluster.global.mbarrier::complete_tx::bytes "
                "[%0], [%1], %2, [%3];"
                :: "r"(dst), "l"(gsrc), "r"(bytes), "r"(mb) : "memory");
        }
    }

    const int warp = threadIdx.x >> 5, lane = threadIdx.x & 31;
    const int y = r0 + warp;
    const float* vx_row = v + (size_t)(b * 2) * DHW + (size_t)d * HW + y * W;
    const float* vy_row = vx_row + DHW;
    float* obase = out + (size_t)(b * C) * DHW + (size_t)d * HW + y * W;

    // half 1 coords overlap the TMA
    Coords cc;
    compute_coords(cc, vx_row, vy_row, lane, y, 0, r_lo, r_hi);

    // wait for TMA tiles
    {
        uint32_t done;
        do {
            asm volatile(
                "{.reg .pred p; mbarrier.try_wait.parity.acquire.cta.shared::cta.b64 "
                "p, [%1], %2; selp.b32 %0, 1, 0, p;}"
                : "=r"(done) : "r"(mb), "r"(0u) : "memory");
        } while (!done);
    }

    gather_store(cc, tile, splane, obase, lane, 0);
    compute_coords(cc, vx_row, vy_row, lane, y, HP, r_lo, r_hi);
    gather_store(cc, tile, splane, obase, lane, HP);
}

extern "C" void kernel_launch(void* const* d_in, const int* in_sizes, int n_in,
                              void* d_out, int out_size)
{
    const float* src = (const float*)d_in[0];
    const float* v   = (const float*)d_in[1];
    float* out       = (float*)d_out;

    cudaFuncSetAttribute(st_kernel,
                         cudaFuncAttributeMaxDynamicSharedMemorySize,
                         (int)SMEM_BYTES);
    st_kernel<<<NBLK, TPB, SMEM_BYTES>>>(src, v, out);
}

// round 5
// speedup vs baseline: 1.7043x; 1.0060x over previous
#include <cuda_runtime.h>
#include <cstdint>

// SpatialTransformer: 2D bilinear warp per depth slice, align_corners=True,
// zero padding. src [B,C,D,H,W] f32, v [B,2,D,H,W] f32, out f32.
// H==W so normalization cancels: ix = x + vx, iy = y + vy.
//
// TMA-stage a 24-row band (16 output rows + 4 margin each side) of all 4
// channel planes into SMEM; gather with LDS (bank = x mod 32); rare
// out-of-band rows (|vy|>4) fall back to global __ldg.
// RB=16 cuts the staging overlap 2.0x -> 1.5x vs RB=8; 512-thread blocks,
// 2 blocks/SM -> 32 resident warps.

constexpr int B = 8, C = 4, D = 32, H = 256, W = 256;
constexpr int HW  = H * W;
constexpr int DHW = D * HW;
constexpr int RB  = 16;                // output rows per block
constexpr int MGN = 4;                 // staged row margin (|vy|<=4 fast path)
constexpr int TRMAX = RB + 2 * MGN;    // 24 staged rows max
constexpr int TPB = 512;               // 16 warps; 1 output row per warp
constexpr int HP  = 4;                 // pixels per half (2 halves = 8 px/thread)
constexpr int TILE_ELEMS = TRMAX * W;  // 6144 floats per channel
constexpr int NBLK = B * D * (H / RB); // 4096
constexpr size_t SMEM_BYTES = (size_t)C * TILE_ELEMS * 4 + 16;

__device__ __forceinline__ uint32_t s2u(const void* p) {
    return (uint32_t)__cvta_generic_to_shared(p);
}

struct Coords {
    int   o00[HP], o01[HP], o10[HP], o11[HP];
    float k00[HP], k01[HP], k10[HP], k11[HP];
};

__device__ __forceinline__ void compute_coords(
    Coords& cc, const float* __restrict__ vx_row, const float* __restrict__ vy_row,
    int lane, int y, int p0, int r_lo, int r_hi)
{
#pragma unroll
    for (int p = 0; p < HP; p++) {
        const int x = lane + 32 * (p0 + p);
        const float vx = __ldg(vx_row + x);
        const float vy = __ldg(vy_row + x);
        const float ix = (float)x + vx;
        const float iy = (float)y + vy;
        const float x0f = floorf(ix), y0f = floorf(iy);
        const float fx = ix - x0f, fy = iy - y0f;
        const int x0 = (int)x0f, y0 = (int)y0f;
        const int x1 = x0 + 1,   y1 = y0 + 1;

        const float mx0 = (x0 >= 0 && x0 < W) ? 1.0f : 0.0f;
        const float mx1 = (x1 >= 0 && x1 < W) ? 1.0f : 0.0f;
        const float my0 = (y0 >= 0 && y0 < H) ? 1.0f : 0.0f;
        const float my1 = (y1 >= 0 && y1 < H) ? 1.0f : 0.0f;

        const int x0c = min(max(x0, 0), W - 1);
        const int x1c = min(max(x1, 0), W - 1);
        const int y0c = min(max(y0, 0), H - 1);
        const int y1c = min(max(y1, 0), H - 1);

        const float gx0 = 1.0f - fx, gy0 = 1.0f - fy;
        cc.k00[p] = gx0 * gy0 * (mx0 * my0);
        cc.k01[p] = fx  * gy0 * (mx1 * my0);
        cc.k10[p] = gx0 * fy  * (mx0 * my1);
        cc.k11[p] = fx  * fy  * (mx1 * my1);

        if (y0c >= r_lo && y1c < r_hi) {
            const int row0 = (y0c - r_lo) * W, row1 = (y1c - r_lo) * W;
            cc.o00[p] = row0 + x0c; cc.o01[p] = row0 + x1c;
            cc.o10[p] = row1 + x0c; cc.o11[p] = row1 + x1c;
        } else {
            // slow path: encode global plane offsets as ~g (negative)
            cc.o00[p] = ~(y0c * W + x0c); cc.o01[p] = ~(y0c * W + x1c);
            cc.o10[p] = ~(y1c * W + x0c); cc.o11[p] = ~(y1c * W + x1c);
        }
    }
}

__device__ __forceinline__ void gather_store(
    const Coords& cc, const float* __restrict__ tile,
    const float* __restrict__ splane, float* __restrict__ obase,
    int lane, int p0)
{
#pragma unroll
    for (int p = 0; p < HP; p++) {
        const int x = lane + 32 * (p0 + p);
        if (cc.o00[p] >= 0) {
#pragma unroll
            for (int c = 0; c < C; c++) {
                const float* tc = tile + c * TILE_ELEMS;
                float acc =      tc[cc.o00[p]] * cc.k00[p];
                acc = fmaf(tc[cc.o01[p]], cc.k01[p], acc);
                acc = fmaf(tc[cc.o10[p]], cc.k10[p], acc);
                acc = fmaf(tc[cc.o11[p]], cc.k11[p], acc);
                obase[(size_t)c * DHW + x] = acc;
            }
        } else {
            const int g00 = ~cc.o00[p], g01 = ~cc.o01[p];
            const int g10 = ~cc.o10[p], g11 = ~cc.o11[p];
#pragma unroll
            for (int c = 0; c < C; c++) {
                const float* sc = splane + (size_t)c * DHW;
                float acc =      __ldg(sc + g00) * cc.k00[p];
                acc = fmaf(__ldg(sc + g01), cc.k01[p], acc);
                acc = fmaf(__ldg(sc + g10), cc.k10[p], acc);
                acc = fmaf(__ldg(sc + g11), cc.k11[p], acc);
                obase[(size_t)c * DHW + x] = acc;
            }
        }
    }
}

__global__ __launch_bounds__(TPB, 2)
void st_kernel(const float* __restrict__ src,
               const float* __restrict__ v,
               float* __restrict__ out)
{
    extern __shared__ float smem[];
    float* tile = smem;  // [C][TILE_ELEMS]
    unsigned long long* mbar = (unsigned long long*)(smem + C * TILE_ELEMS);

    const int blk = blockIdx.x;
    const int rt  = blk & (H / RB - 1);   // 16 row-tiles
    const int bd  = blk >> 4;
    const int d   = bd & (D - 1);
    const int b   = bd >> 5;
    const int r0  = rt * RB;
    const int r_lo = max(0, r0 - MGN);
    const int r_hi = min(H, r0 + RB + MGN);
    const int nrows = r_hi - r_lo;

    const float* splane = src + (size_t)(b * C) * DHW + (size_t)d * HW;

    const uint32_t mb = s2u(mbar);
    if (threadIdx.x == 0) {
        asm volatile("mbarrier.init.shared.b64 [%0], 1;" :: "r"(mb) : "memory");
    }
    __syncthreads();
    if (threadIdx.x == 0) {
        const int bytes = nrows * W * 4;
        asm volatile("mbarrier.arrive.expect_tx.shared.b64 _, [%0], %1;"
                     :: "r"(mb), "r"(bytes * C) : "memory");
#pragma unroll
        for (int c = 0; c < C; c++) {
            const uint32_t dst = s2u(tile + c * TILE_ELEMS);
            const float* gsrc = splane + (size_t)c * DHW + r_lo * W;
            asm volatile(
                "cp.async.bulk.shared::cluster.global.mbarrier::complete_tx::bytes "
                "[%0], [%1], %2, [%3];"
                :: "r"(dst), "l"(gsrc), "r"(bytes), "r"(mb) : "memory");
        }
    }

    const int warp = threadIdx.x >> 5, lane = threadIdx.x & 31;
    const int y = r0 + warp;
    const float* vx_row = v + (size_t)(b * 2) * DHW + (size_t)d * HW + y * W;
    const float* vy_row = vx_row + DHW;
    float* obase = out + (size_t)(b * C) * DHW + (size_t)d * HW + y * W;

    // half 1 coords overlap the TMA
    Coords cc;
    compute_coords(cc, vx_row, vy_row, lane, y, 0, r_lo, r_hi);

    // wait for TMA tiles
    {
        uint32_t done;
        do {
            asm volatile(
                "{.reg .pred p; mbarrier.try_wait.parity.acquire.cta.shared::cta.b64 "
                "p, [%1], %2; selp.b32 %0, 1, 0, p;}"
                : "=r"(done) : "r"(mb), "r"(0u) : "memory");
        } while (!done);
    }

    gather_store(cc, tile, splane, obase, lane, 0);
    compute_coords(cc, vx_row, vy_row, lane, y, HP, r_lo, r_hi);
    gather_store(cc, tile, splane, obase, lane, HP);
}

extern "C" void kernel_launch(void* const* d_in, const int* in_sizes, int n_in,
                              void* d_out, int out_size)
{
    const float* src = (const float*)d_in[0];
    const float* v   = (const float*)d_in[1];
    float* out       = (float*)d_out;

    cudaFuncSetAttribute(st_kernel,
                         cudaFuncAttributeMaxDynamicSharedMemorySize,
                         (int)SMEM_BYTES);
    st_kernel<<<NBLK, TPB, SMEM_BYTES>>>(src, v, out);
}

// round 6
// speedup vs baseline: 1.7256x; 1.0125x over previous
#include <cuda_runtime.h>
#include <cstdint>

// SpatialTransformer: 2D bilinear warp per depth slice, align_corners=True,
// zero padding. src [B,C,D,H,W] f32, v [B,2,D,H,W] f32, out f32.
// H==W so normalization cancels: ix = x + vx, iy = y + vy.
//
// TMA-stage a 24-row band (16 output rows + 4 margin each side) of all 4
// channel planes into SMEM; gather with LDS (bank = x mod 32); rare
// out-of-band rows (|vy|>4) fall back to global __ldg.
// RB=16 cuts the staging overlap 2.0x -> 1.5x vs RB=8; 512-thread blocks,
// 2 blocks/SM -> 32 resident warps.

constexpr int B = 8, C = 4, D = 32, H = 256, W = 256;
constexpr int HW  = H * W;
constexpr int DHW = D * HW;
constexpr int RB  = 16;                // output rows per block
constexpr int MGN = 4;                 // staged row margin (|vy|<=4 fast path)
constexpr int TRMAX = RB + 2 * MGN;    // 24 staged rows max
constexpr int TPB = 512;               // 16 warps; 1 output row per warp
constexpr int HP  = 4;                 // pixels per half (2 halves = 8 px/thread)
constexpr int TILE_ELEMS = TRMAX * W;  // 6144 floats per channel
constexpr int NBLK = B * D * (H / RB); // 4096
constexpr size_t SMEM_BYTES = (size_t)C * TILE_ELEMS * 4 + 16;

__device__ __forceinline__ uint32_t s2u(const void* p) {
    return (uint32_t)__cvta_generic_to_shared(p);
}

struct Coords {
    int   o00[HP], o01[HP], o10[HP], o11[HP];
    float k00[HP], k01[HP], k10[HP], k11[HP];
};

__device__ __forceinline__ void compute_coords(
    Coords& cc, const float* __restrict__ vx_row, const float* __restrict__ vy_row,
    int lane, int y, int p0, int r_lo, int r_hi)
{
#pragma unroll
    for (int p = 0; p < HP; p++) {
        const int x = lane + 32 * (p0 + p);
        const float vx = __ldg(vx_row + x);
        const float vy = __ldg(vy_row + x);
        const float ix = (float)x + vx;
        const float iy = (float)y + vy;
        const float x0f = floorf(ix), y0f = floorf(iy);
        const float fx = ix - x0f, fy = iy - y0f;
        const int x0 = (int)x0f, y0 = (int)y0f;
        const int x1 = x0 + 1,   y1 = y0 + 1;

        const float mx0 = (x0 >= 0 && x0 < W) ? 1.0f : 0.0f;
        const float mx1 = (x1 >= 0 && x1 < W) ? 1.0f : 0.0f;
        const float my0 = (y0 >= 0 && y0 < H) ? 1.0f : 0.0f;
        const float my1 = (y1 >= 0 && y1 < H) ? 1.0f : 0.0f;

        const int x0c = min(max(x0, 0), W - 1);
        const int x1c = min(max(x1, 0), W - 1);
        const int y0c = min(max(y0, 0), H - 1);
        const int y1c = min(max(y1, 0), H - 1);

        const float gx0 = 1.0f - fx, gy0 = 1.0f - fy;
        cc.k00[p] = gx0 * gy0 * (mx0 * my0);
        cc.k01[p] = fx  * gy0 * (mx1 * my0);
        cc.k10[p] = gx0 * fy  * (mx0 * my1);
        cc.k11[p] = fx  * fy  * (mx1 * my1);

        if (y0c >= r_lo && y1c < r_hi) {
            const int row0 = (y0c - r_lo) * W, row1 = (y1c - r_lo) * W;
            cc.o00[p] = row0 + x0c; cc.o01[p] = row0 + x1c;
            cc.o10[p] = row1 + x0c; cc.o11[p] = row1 + x1c;
        } else {
            // slow path: encode global plane offsets as ~g (negative)
            cc.o00[p] = ~(y0c * W + x0c); cc.o01[p] = ~(y0c * W + x1c);
            cc.o10[p] = ~(y1c * W + x0c); cc.o11[p] = ~(y1c * W + x1c);
        }
    }
}

__device__ __forceinline__ void gather_store(
    const Coords& cc, const float* __restrict__ tile,
    const float* __restrict__ splane, float* __restrict__ obase,
    int lane, int p0)
{
#pragma unroll
    for (int p = 0; p < HP; p++) {
        const int x = lane + 32 * (p0 + p);
        if (cc.o00[p] >= 0) {
#pragma unroll
            for (int c = 0; c < C; c++) {
                const float* tc = tile + c * TILE_ELEMS;
                float acc =      tc[cc.o00[p]] * cc.k00[p];
                acc = fmaf(tc[cc.o01[p]], cc.k01[p], acc);
                acc = fmaf(tc[cc.o10[p]], cc.k10[p], acc);
                acc = fmaf(tc[cc.o11[p]], cc.k11[p], acc);
                obase[(size_t)c * DHW + x] = acc;
            }
        } else {
            const int g00 = ~cc.o00[p], g01 = ~cc.o01[p];
            const int g10 = ~cc.o10[p], g11 = ~cc.o11[p];
#pragma unroll
            for (int c = 0; c < C; c++) {
                const float* sc = splane + (size_t)c * DHW;
                float acc =      __ldg(sc + g00) * cc.k00[p];
                acc = fmaf(__ldg(sc + g01), cc.k01[p], acc);
                acc = fmaf(__ldg(sc + g10), cc.k10[p], acc);
                acc = fmaf(__ldg(sc + g11), cc.k11[p], acc);
                obase[(size_t)c * DHW + x] = acc;
            }
        }
    }
}

__global__ __launch_bounds__(TPB, 2)
void st_kernel(const float* __restrict__ src,
               const float* __restrict__ v,
               float* __restrict__ out)
{
    extern __shared__ float smem[];
    float* tile = smem;  // [C][TILE_ELEMS]
    unsigned long long* mbar = (unsigned long long*)(smem + C * TILE_ELEMS);

    const int blk = blockIdx.x;
    const int rt  = blk & (H / RB - 1);   // 16 row-tiles
    const int bd  = blk >> 4;
    const int d   = bd & (D - 1);
    const int b   = bd >> 5;
    const int r0  = rt * RB;
    const int r_lo = max(0, r0 - MGN);
    const int r_hi = min(H, r0 + RB + MGN);
    const int nrows = r_hi - r_lo;

    const float* splane = src + (size_t)(b * C) * DHW + (size_t)d * HW;

    const uint32_t mb = s2u(mbar);
    if (threadIdx.x == 0) {
        asm volatile("mbarrier.init.shared.b64 [%0], 1;" :: "r"(mb) : "memory");
    }
    __syncthreads();
    if (threadIdx.x == 0) {
        const int bytes = nrows * W * 4;
        asm volatile("mbarrier.arrive.expect_tx.shared.b64 _, [%0], %1;"
                     :: "r"(mb), "r"(bytes * C) : "memory");
#pragma unroll
        for (int c = 0; c < C; c++) {
            const uint32_t dst = s2u(tile + c * TILE_ELEMS);
            const float* gsrc = splane + (size_t)c * DHW + r_lo * W;
            asm volatile(
                "cp.async.bulk.shared::cluster.global.mbarrier::complete_tx::bytes "
                "[%0], [%1], %2, [%3];"
                :: "r"(dst), "l"(gsrc), "r"(bytes), "r"(mb) : "memory");
        }
    }

    const int warp = threadIdx.x >> 5, lane = threadIdx.x & 31;
    const int y = r0 + warp;
    const float* vx_row = v + (size_t)(b * 2) * DHW + (size_t)d * HW + y * W;
    const float* vy_row = vx_row + DHW;
    float* obase = out + (size_t)(b * C) * DHW + (size_t)d * HW + y * W;

    // half 1 coords overlap the TMA
    Coords cc;
    compute_coords(cc, vx_row, vy_row, lane, y, 0, r_lo, r_hi);

    // wait for TMA tiles
    {
        uint32_t done;
        do {
            asm volatile(
                "{.reg .pred p; mbarrier.try_wait.parity.acquire.cta.shared::cta.b64 "
                "p, [%1], %2; selp.b32 %0, 1, 0, p;}"
                : "=r"(done) : "r"(mb), "r"(0u) : "memory");
        } while (!done);
    }

    gather_store(cc, tile, splane, obase, lane, 0);
    compute_coords(cc, vx_row, vy_row, lane, y, HP, r_lo, r_hi);
    gather_store(cc, tile, splane, obase, lane, HP);
}

extern "C" void kernel_launch(void* const* d_in, const int* in_sizes, int n_in,
                              void* d_out, int out_size)
{
    const float* src = (const float*)d_in[0];
    const float* v   = (const float*)d_in[1];
    float* out       = (float*)d_out;

    cudaFuncSetAttribute(st_kernel,
                         cudaFuncAttributeMaxDynamicSharedMemorySize,
                         (int)SMEM_BYTES);
    st_kernel<<<NBLK, TPB, SMEM_BYTES>>>(src, v, out);
}